// round 7
// baseline (speedup 1.0000x reference)
#include <cuda_runtime.h>
#include <cstdint>

// Problem shape (fixed by the dataset): T=8, B=32, C=128, H=32, W=32
// x_accum: [T,B,C,H,W] fp32, out spikes: [T,B,C,H,W] fp32
// N_per_t = B*C*H*W = 4,194,304 elements = 1,048,576 float4
// Per-t stride between time planes = 1,048,576 float4.

#define T_STEPS 8
#define VEC_PER_T 1048576u       // (32*128*32*32)/4
#define EPS 1e-12f

__device__ __forceinline__ float decode_scalar_f(const void* p) {
    // Input may be int32 or float32 encoded; value is a small positive int (tau)
    int iv = *reinterpret_cast<const int*>(p);
    if (iv >= 1 && iv <= (1 << 23)) return (float)iv;   // plausible int32
    return __int_as_float(iv);                          // else treat bits as float
}

__global__ void __launch_bounds__(256)
integer_neuron_kernel(const float* __restrict__ x,
                      const float* __restrict__ prev_scale,
                      const float* __restrict__ prev_bias,
                      const float* __restrict__ vth,
                      const void* __restrict__ tau_p,
                      const int*  __restrict__ first_p,
                      float* __restrict__ out)
{
    const unsigned vec = blockIdx.x * 256u + threadIdx.x;   // float4 index within one t-plane

    // ---- per-channel constants (c is uniform within a block: 256 thr * 4 = 1024 = H*W) ----
    const int c = (int)((vec >> 8) & 127u);                 // (vec*4)/1024 mod 128
    const float tau_f  = decode_scalar_f(tau_p);
    const bool  first  = (first_p[0] != 0);
    const float s_eps  = __fadd_rn(prev_scale[c], EPS);
    const float bias_s = rintf(__fdiv_rn(__fmul_rn(prev_bias[c], tau_f), s_eps));
    const float vth_s  = rintf(__fdiv_rn(__fmul_rn(vth[0],       tau_f), s_eps));

    const float4* xp = reinterpret_cast<const float4*>(x);
    float4*       op = reinterpret_cast<float4*>(out);

    // ---- hoist all T loads: MLP=8 LDG.128 per thread ----
    float4 xv[T_STEPS];
#pragma unroll
    for (int t = 0; t < T_STEPS; t++)
        xv[t] = xp[(size_t)t * VEC_PER_T + vec];

    const float mul = first ? 1.0f : tau_f;

    float4 m = make_float4(0.f, 0.f, 0.f, 0.f);
#pragma unroll
    for (int t = 0; t < T_STEPS; t++) {
        float4 v = xv[t];
        // drive = x (or x*tau). Explicit rn intrinsics: no FMA contraction, so the
        // accumulation sequence is bit-identical to the JAX reference:
        //   mem = (mem + x_t) + bias_scaled
        float dx = __fmul_rn(v.x, mul);
        float dy = __fmul_rn(v.y, mul);
        float dz = __fmul_rn(v.z, mul);
        float dw = __fmul_rn(v.w, mul);

        m.x = __fadd_rn(__fadd_rn(m.x, dx), bias_s);
        m.y = __fadd_rn(__fadd_rn(m.y, dy), bias_s);
        m.z = __fadd_rn(__fadd_rn(m.z, dz), bias_s);
        m.w = __fadd_rn(__fadd_rn(m.w, dw), bias_s);

        float4 spk;
        spk.x = (m.x >= vth_s) ? 1.0f : 0.0f;
        spk.y = (m.y >= vth_s) ? 1.0f : 0.0f;
        spk.z = (m.z >= vth_s) ? 1.0f : 0.0f;
        spk.w = (m.w >= vth_s) ? 1.0f : 0.0f;

        // soft reset: mem -= spike*vth_scaled  (spike is exactly 0 or 1)
        if (spk.x != 0.0f) m.x = __fsub_rn(m.x, vth_s);
        if (spk.y != 0.0f) m.y = __fsub_rn(m.y, vth_s);
        if (spk.z != 0.0f) m.z = __fsub_rn(m.z, vth_s);
        if (spk.w != 0.0f) m.w = __fsub_rn(m.w, vth_s);

        op[(size_t)t * VEC_PER_T + vec] = spk;
    }
}

extern "C" void kernel_launch(void* const* d_in, const int* in_sizes, int n_in,
                              void* d_out, int out_size)
{
    // metadata order: x_accum, prev_scale, prev_bias, vth, tau, is_first_layer
    const float* x     = (const float*)d_in[0];
    const float* scale = (const float*)d_in[1];
    const float* bias  = (const float*)d_in[2];
    const float* vth   = (const float*)d_in[3];
    const void*  tau   = d_in[4];
    const int*   first = (const int*)d_in[5];
    float* out = (float*)d_out;

    (void)in_sizes; (void)n_in; (void)out_size;

    dim3 grid(VEC_PER_T / 256u);   // 4096 blocks
    dim3 block(256);
    integer_neuron_kernel<<<grid, block>>>(x, scale, bias, vth, tau, first, out);
}

// round 12
// speedup vs baseline: 1.0092x; 1.0092x over previous
#include <cuda_runtime.h>
#include <cstdint>

// Problem shape (fixed): T=8, B=32, C=128, H=32, W=32
// x_accum: [T,B,C,H,W] fp32 -> spikes [T,B,C,H,W] fp32 (LIF scan over T).
// Pure HBM streaming: 128 MiB in + 128 MiB out. Roofline floor ~36-40us.

#define T_STEPS 8
#define VEC_PER_T 1048576u       // (32*128*32*32)/4 float4 per t-plane
#define EPS 1e-12f

__device__ __forceinline__ float decode_scalar_f(const void* p) {
    // tau may arrive as int32 or float32; decode defensively.
    int iv = *reinterpret_cast<const int*>(p);
    if (iv >= 1 && iv <= (1 << 23)) return (float)iv;   // plausible int32
    return __int_as_float(iv);                          // else raw float bits
}

__global__ void __launch_bounds__(256, 4)   // reg budget ~56: keep all 8 LDG.128 in flight
integer_neuron_kernel(const float* __restrict__ x,
                      const float* __restrict__ prev_scale,
                      const float* __restrict__ prev_bias,
                      const float* __restrict__ vth,
                      const void* __restrict__ tau_p,
                      const int*  __restrict__ first_p,
                      float* __restrict__ out)
{
    const unsigned vec = blockIdx.x * 256u + threadIdx.x;   // float4 index in one t-plane

    // Channel is uniform per block (256 thr * 4 elem = 1024 = H*W = one channel plane).
    const int c = (int)((vec >> 8) & 127u);
    const float tau_f  = decode_scalar_f(tau_p);
    const bool  first  = (__ldg(first_p) != 0);
    const float s_eps  = __fadd_rn(__ldg(prev_scale + c), EPS);
    const float bias_s = rintf(__fdiv_rn(__fmul_rn(__ldg(prev_bias + c), tau_f), s_eps));
    const float vth_s  = rintf(__fdiv_rn(__fmul_rn(__ldg(vth),           tau_f), s_eps));
    const float nvth_s = -vth_s;
    const float mul    = first ? 1.0f : tau_f;

    const float4* xp = reinterpret_cast<const float4*>(x) + vec;
    float4*       op = reinterpret_cast<float4*>(out) + vec;

    // ---- hoist all T loads with streaming (evict-first) policy: MLP=8 LDG.128.CS ----
    float4 xv[T_STEPS];
#pragma unroll
    for (int t = 0; t < T_STEPS; t++)
        xv[t] = __ldcs(xp + (size_t)t * VEC_PER_T);

    float4 m = make_float4(0.f, 0.f, 0.f, 0.f);
#pragma unroll
    for (int t = 0; t < T_STEPS; t++) {
        float4 v = xv[t];
        // Bit-exact vs reference: mem = (mem + x_t*mul) + bias_scaled, all rn,
        // no contraction across the adds.
        m.x = __fadd_rn(__fadd_rn(m.x, __fmul_rn(v.x, mul)), bias_s);
        m.y = __fadd_rn(__fadd_rn(m.y, __fmul_rn(v.y, mul)), bias_s);
        m.z = __fadd_rn(__fadd_rn(m.z, __fmul_rn(v.z, mul)), bias_s);
        m.w = __fadd_rn(__fadd_rn(m.w, __fmul_rn(v.w, mul)), bias_s);

        float4 spk;
        spk.x = (m.x >= vth_s) ? 1.0f : 0.0f;
        spk.y = (m.y >= vth_s) ? 1.0f : 0.0f;
        spk.z = (m.z >= vth_s) ? 1.0f : 0.0f;
        spk.w = (m.w >= vth_s) ? 1.0f : 0.0f;

        // soft reset: mem -= spk*vth. spk*vth_s is exact (0 or vth_s), so the
        // single-rounded FMA is bit-identical to rn(m - spk*vth). Branch-free.
        m.x = __fmaf_rn(spk.x, nvth_s, m.x);
        m.y = __fmaf_rn(spk.y, nvth_s, m.y);
        m.z = __fmaf_rn(spk.z, nvth_s, m.z);
        m.w = __fmaf_rn(spk.w, nvth_s, m.w);

        __stcs(op + (size_t)t * VEC_PER_T, spk);   // streaming store, evict-first
    }
}

extern "C" void kernel_launch(void* const* d_in, const int* in_sizes, int n_in,
                              void* d_out, int out_size)
{
    // metadata order: x_accum, prev_scale, prev_bias, vth, tau, is_first_layer
    const float* x     = (const float*)d_in[0];
    const float* scale = (const float*)d_in[1];
    const float* bias  = (const float*)d_in[2];
    const float* vth   = (const float*)d_in[3];
    const void*  tau   = d_in[4];
    const int*   first = (const int*)d_in[5];
    float* out = (float*)d_out;

    (void)in_sizes; (void)n_in; (void)out_size;

    integer_neuron_kernel<<<VEC_PER_T / 256u, 256>>>(x, scale, bias, vth, tau, first, out);
}